// round 12
// baseline (speedup 1.0000x reference)
#include <cuda_runtime.h>
#include <cuda_fp16.h>
#include <cstdint>

#define B_  16
#define N_  2048
#define D_  128
#define BM  128
#define BN  64
#define NT  256
#define NTP 256
#define NTILES (N_/BN)        // 32
#define RS  272               // smem row stride (bytes)
#define TS  (64*RS)           // one 64x128 fp16 tile = 17408 B
#define CAP_C 128             // global candidate cap per row
#define CAP_S 24              // smem survivor cap per row

// smem layout
#define SM_STAGES (4*TS)                  // {Kh,Vh} x 2 stages = 69632
#define SM_SCNT   SM_STAGES               // 128 ints
#define SM_SURCNT (SM_SCNT + 512)         // 128 ints
#define SM_SUR    (SM_SURCNT + 512)       // 128 x CAP_S x 8B = 24576
#define SMEM_TOTAL (SM_SUR + 128*CAP_S*8) // 95232

// -------- static device scratch --------
__device__ __align__(256) __half g_Qh[B_*N_*D_];   // q * log2e, fp16
__device__ __align__(256) __half g_Kh[B_*N_*D_];
__device__ __align__(256) __half g_Vh[B_*N_*D_];
__device__ __align__(256) unsigned long long g_cand[(size_t)B_*N_*CAP_C];  // 33.5 MB

// -------- PTX helpers (compute_103-safe) --------
__device__ __forceinline__ uint32_t smem_u32(const void* p) {
    uint32_t a;
    asm("{ .reg .u64 t; cvta.to.shared.u64 t, %1; cvt.u32.u64 %0, t; }" : "=r"(a) : "l"(p));
    return a;
}
__device__ __forceinline__ void cpa16(uint32_t dst, const void* src) {
    asm volatile("cp.async.cg.shared.global [%0], [%1], 16;" :: "r"(dst), "l"(src) : "memory");
}
#define CP_COMMIT() asm volatile("cp.async.commit_group;" ::: "memory")
#define CP_WAIT(n)  asm volatile("cp.async.wait_group %0;" :: "n"(n) : "memory")

__device__ __forceinline__ void ldsm4(uint32_t* r, uint32_t a) {
    asm volatile("ldmatrix.sync.aligned.m8n8.x4.shared.b16 {%0,%1,%2,%3}, [%4];"
        : "=r"(r[0]), "=r"(r[1]), "=r"(r[2]), "=r"(r[3]) : "r"(a));
}
__device__ __forceinline__ void ldsm4t(uint32_t* r, uint32_t a) {
    asm volatile("ldmatrix.sync.aligned.m8n8.x4.trans.shared.b16 {%0,%1,%2,%3}, [%4];"
        : "=r"(r[0]), "=r"(r[1]), "=r"(r[2]), "=r"(r[3]) : "r"(a));
}
__device__ __forceinline__ void mma16816(float* c, const uint32_t* a, uint32_t b0, uint32_t b1) {
    asm volatile(
        "mma.sync.aligned.m16n8k16.row.col.f32.f16.f16.f32 "
        "{%0,%1,%2,%3}, {%4,%5,%6,%7}, {%8,%9}, {%0,%1,%2,%3};"
        : "+f"(c[0]), "+f"(c[1]), "+f"(c[2]), "+f"(c[3])
        : "r"(a[0]), "r"(a[1]), "r"(a[2]), "r"(a[3]), "r"(b0), "r"(b1));
}
__device__ __forceinline__ uint32_t pack_h2(float a, float b) {
    __half2 h = __floats2half2_rn(a, b);
    return *(uint32_t*)&h;
}
__device__ __forceinline__ float ex2(float x) {
    float r;
    asm("ex2.approx.ftz.f32 %0, %1;" : "=f"(r) : "f"(x));
    return r;
}

// -------- prep: Q*log2e -> fp16, K -> fp16, V -> fp16 --------
__global__ void prep_kernel(const float* __restrict__ Q, const float* __restrict__ K,
                            const float* __restrict__ V) {
    size_t i = (size_t)blockIdx.x * blockDim.x + threadIdx.x;
    float2 q = ((const float2*)Q)[i];
    ((__half2*)g_Qh)[i] = __floats2half2_rn(q.x * 1.44269504089f, q.y * 1.44269504089f);
    float2 k = ((const float2*)K)[i];
    ((__half2*)g_Kh)[i] = __floats2half2_rn(k.x, k.y);
    float2 v = ((const float2*)V)[i];
    ((__half2*)g_Vh)[i] = __floats2half2_rn(v.x, v.y);
}

// -------- smem loaders --------
__device__ __forceinline__ void cp_tile64(uint32_t dstbase, const __half* src, int tid) {
#pragma unroll
    for (int i = 0; i < 4; i++) {
        int g = tid + i * NT;
        int row = g >> 4, c = g & 15;
        cpa16(dstbase + row * RS + c * 16, (const char*)src + row * 256 + c * 16);
    }
}
__device__ __forceinline__ void cp_tile128(uint32_t dstbase, const __half* src, int tid) {
#pragma unroll
    for (int i = 0; i < 8; i++) {
        int g = tid + i * NT;
        int row = g >> 4, c = g & 15;
        cpa16(dstbase + row * RS + c * 16, (const char*)src + row * 256 + c * 16);
    }
}
__device__ __forceinline__ void issue_group(uint32_t sb, size_t kvbase, int u, int tid) {
    size_t off = kvbase + (size_t)u * BN * D_;
    uint32_t st = sb + (uint32_t)(u & 1) * (2 * TS);
    cp_tile64(st,      g_Kh + off, tid);
    cp_tile64(st + TS, g_Vh + off, tid);
}

// -------- main attention kernel --------
__global__ void __launch_bounds__(NT, 1)
attn_refine_kernel(const float* __restrict__ Qf, const float* __restrict__ Kf,
                   const float* __restrict__ Vf, float* __restrict__ O)
{
    extern __shared__ __align__(1024) char smem[];
    uint32_t sb = smem_u32(smem);
    int* scnt    = (int*)(smem + SM_SCNT);
    int* surcnt  = (int*)(smem + SM_SURCNT);
    float2* sur  = (float2*)(smem + SM_SUR);

    const int tid  = threadIdx.x;
    const int warp = tid >> 5;
    const int lane = tid & 31;
    const int qt = blockIdx.x;
    const int b  = blockIdx.y;

    const int m0 = warp * 16;
    const uint32_t qrow = m0 + (lane & 7) + ((lane & 8) ? 8 : 0);
    const uint32_t krow = (lane & 7) + ((lane & 16) ? 8 : 0);
    const uint32_t kcol = (lane & 8) ? 16 : 0;
    const uint32_t vrow = (lane & 7) + ((lane & 8) ? 8 : 0);
    const uint32_t vcol = (lane & 16) ? 16 : 0;
    const int lrow0 = m0 + (lane >> 2);
    const int lrow1 = lrow0 + 8;
    const int growbase = b * N_ + qt * BM;     // global row of local row 0

    // zero counters
    if (tid < 128) { scnt[tid] = 0; surcnt[tid] = 0; }

    // ---- stage Q through stage area, hoist fragments, recycle ----
    const size_t qoff = ((size_t)b * N_ + (size_t)qt * BM) * D_;
    cp_tile128(sb, g_Qh + qoff, tid);
    CP_COMMIT();
    CP_WAIT(0);
    __syncthreads();

    uint32_t qfh[8][4];
    {
        const uint32_t aq = sb + qrow * RS + ((lane & 16) ? 16 : 0);
#pragma unroll
        for (int k = 0; k < 8; k++) ldsm4(qfh[k], aq + k * 32);
    }
    __syncthreads();

    const size_t kvbase = (size_t)b * N_ * D_;
    issue_group(sb, kvbase, 0, tid); CP_COMMIT();
    issue_group(sb, kvbase, 1, tid); CP_COMMIT();

    float o[16][4];
#pragma unroll
    for (int i = 0; i < 16; i++)
#pragma unroll
        for (int j = 0; j < 4; j++) o[i][j] = 0.f;
    float m0r = -INFINITY, m1r = -INFINITY, l0 = 0.f, l1 = 0.f;

    CP_WAIT(1);
    __syncthreads();

    for (int t = 0; t < NTILES; t++) {
        const uint32_t st  = sb + (uint32_t)(t & 1) * (2 * TS);
        const uint32_t akh = st + krow * RS + kcol;
        const uint32_t avh = st + TS + vrow * RS + vcol;

        // ---- S(t) = Qh Kh^T (1 term, log2 units) ----
        float s[8][4];
#pragma unroll
        for (int i = 0; i < 8; i++)
#pragma unroll
            for (int j = 0; j < 4; j++) s[i][j] = 0.f;
#pragma unroll
        for (int k = 0; k < 8; k++) {
#pragma unroll
            for (int p = 0; p < 4; p++) {
                uint32_t bh[4];
                ldsm4(bh, akh + p * (16 * RS) + k * 32);
                mma16816(s[2*p],   qfh[k], bh[0], bh[1]);
                mma16816(s[2*p+1], qfh[k], bh[2], bh[3]);
            }
        }

        // ---- row max (running) ----
        float mx0 = s[0][0], mx1 = s[0][2];
#pragma unroll
        for (int nt = 0; nt < 8; nt++) {
            mx0 = fmaxf(mx0, fmaxf(s[nt][0], s[nt][1]));
            mx1 = fmaxf(mx1, fmaxf(s[nt][2], s[nt][3]));
        }
        mx0 = fmaxf(mx0, __shfl_xor_sync(0xffffffffu, mx0, 1));
        mx0 = fmaxf(mx0, __shfl_xor_sync(0xffffffffu, mx0, 2));
        mx1 = fmaxf(mx1, __shfl_xor_sync(0xffffffffu, mx1, 1));
        mx1 = fmaxf(mx1, __shfl_xor_sync(0xffffffffu, mx1, 2));
        float mn0 = fmaxf(m0r, mx0), mn1 = fmaxf(m1r, mx1);

        // ---- candidate detection: s > running_max - 10 (log2) ----
        {
            float thr0 = mn0 - 10.0f, thr1 = mn1 - 10.0f;
#pragma unroll
            for (int nt = 0; nt < 8; nt++) {
#pragma unroll
                for (int e = 0; e < 4; e++) {
                    float sv = s[nt][e];
                    if (sv > ((e < 2) ? thr0 : thr1)) {
                        int lr = (e < 2) ? lrow0 : lrow1;
                        int j = t * 64 + (nt >> 1) * 16 + (nt & 1) * 8 + 2 * (lane & 3) + (e & 1);
                        int ix = atomicAdd(&scnt[lr], 1);
                        if (ix < CAP_C)
                            g_cand[((size_t)(growbase + lr)) * CAP_C + ix] =
                                ((unsigned long long)__float_as_uint(sv) << 32) | (unsigned)j;
                    }
                }
            }
        }

        // ---- online softmax ----
        float c0 = ex2(m0r - mn0), c1 = ex2(m1r - mn1);
        m0r = mn0; m1r = mn1;
        float a0 = 0.f, a1 = 0.f;
#pragma unroll
        for (int nt = 0; nt < 8; nt++) {
            s[nt][0] = ex2(s[nt][0] - mn0); a0 += s[nt][0];
            s[nt][1] = ex2(s[nt][1] - mn0); a0 += s[nt][1];
            s[nt][2] = ex2(s[nt][2] - mn1); a1 += s[nt][2];
            s[nt][3] = ex2(s[nt][3] - mn1); a1 += s[nt][3];
        }
        l0 = l0 * c0 + a0;
        l1 = l1 * c1 + a1;
#pragma unroll
        for (int nt = 0; nt < 16; nt++) {
            o[nt][0] *= c0; o[nt][1] *= c0;
            o[nt][2] *= c1; o[nt][3] *= c1;
        }

        // ---- pack P and PV ----
        uint32_t pha[4][4];
#pragma unroll
        for (int js = 0; js < 4; js++) {
            const float* s0p = s[2*js];
            const float* s1p = s[2*js+1];
            pha[js][0] = pack_h2(s0p[0], s0p[1]);
            pha[js][1] = pack_h2(s0p[2], s0p[3]);
            pha[js][2] = pack_h2(s1p[0], s1p[1]);
            pha[js][3] = pack_h2(s1p[2], s1p[3]);
        }
#pragma unroll
        for (int js = 0; js < 4; js++) {
#pragma unroll
            for (int p = 0; p < 8; p++) {
                uint32_t vh[4];
                ldsm4t(vh, avh + js * (16 * RS) + p * 32);
                mma16816(o[2*p],   pha[js], vh[0], vh[1]);
                mma16816(o[2*p+1], pha[js], vh[2], vh[3]);
            }
        }

        // ---- rotate pipeline ----
        __syncthreads();
        if (t + 2 < NTILES) {
            issue_group(sb, kvbase, t + 2, tid);
            CP_COMMIT();
            CP_WAIT(1);
        } else {
            CP_COMMIT();
            CP_WAIT(0);
        }
        __syncthreads();
    }

    // ================= refinement =================
    __threadfence_block();
    __syncthreads();

    // phase 1: lane-parallel exact rescoring of surviving candidates
    for (int rr = 0; rr < 16; rr++) {
        int lr = m0 + rr;
        int src = (rr & 7) * 4;
        float mf = (rr < 8) ? __shfl_sync(0xffffffffu, m0r, src)
                            : __shfl_sync(0xffffffffu, m1r, src);
        int n = min(scnt[lr], CAP_C);
        size_t cbase = ((size_t)(growbase + lr)) * CAP_C;
        const float4* q4 = (const float4*)(Qf + (size_t)(growbase + lr) * D_);
        for (int c = lane; c < n; c += 32) {
            unsigned long long pk = g_cand[cbase + c];
            float sap = __uint_as_float((uint32_t)(pk >> 32));
            if (sap <= mf - 10.0f) continue;         // prune vs FINAL max
            int j = (int)(pk & 0xffffffffu);
            const float4* k4 = (const float4*)(Kf + ((size_t)b * N_ + j) * D_);
            float dot = 0.f;
#pragma unroll 8
            for (int d = 0; d < 32; d++) {
                float4 qa = q4[d], kb = k4[d];
                dot += qa.x * kb.x + qa.y * kb.y + qa.z * kb.z + qa.w * kb.w;
            }
            float sex = dot * 1.44269504089f;
            float dp = ex2(sex - mf) - ex2(sap - mf);
            int ix = atomicAdd(&surcnt[lr], 1);
            if (ix < CAP_S) sur[lr * CAP_S + ix] = make_float2(dp, __int_as_float(j));
        }
    }
    __syncthreads();

    // phase 2: owner threads apply v-updates and l fix
    const int cbase2 = 2 * (lane & 3);
    float dl0 = 0.f, dl1 = 0.f;
#pragma unroll
    for (int h = 0; h < 2; h++) {
        int lr = (h ? lrow1 : lrow0);
        int n = min(surcnt[lr], CAP_S);
        for (int c = 0; c < n; c++) {
            float2 e = sur[lr * CAP_S + c];
            float dp = e.x;
            int j = __float_as_int(e.y);
            if (h) dl1 += dp; else dl0 += dp;
            const float* vrowp = Vf + ((size_t)b * N_ + j) * D_;
#pragma unroll
            for (int nt = 0; nt < 16; nt++) {
                float2 vv = *(const float2*)(vrowp + nt * 8 + cbase2);
                o[nt][2*h]     += dp * vv.x;
                o[nt][2*h + 1] += dp * vv.y;
            }
        }
    }

    // ---- epilogue ----
    l0 += __shfl_xor_sync(0xffffffffu, l0, 1);
    l0 += __shfl_xor_sync(0xffffffffu, l0, 2);
    l1 += __shfl_xor_sync(0xffffffffu, l1, 1);
    l1 += __shfl_xor_sync(0xffffffffu, l1, 2);
    l0 += dl0;
    l1 += dl1;
    float inv0 = 1.0f / l0, inv1 = 1.0f / l1;

    size_t row0 = (size_t)b * N_ + (size_t)qt * BM + m0 + (lane >> 2);
    float* p0 = O + row0 * D_;
    float* p1 = p0 + 8 * D_;
#pragma unroll
    for (int nt = 0; nt < 16; nt++) {
        int c = nt * 8 + cbase2;
        *(float2*)(p0 + c) = make_float2(o[nt][0] * inv0, o[nt][1] * inv0);
        *(float2*)(p1 + c) = make_float2(o[nt][2] * inv1, o[nt][3] * inv1);
    }
}

// -------- launcher --------
extern "C" void kernel_launch(void* const* d_in, const int* in_sizes, int n_in,
                              void* d_out, int out_size) {
    const float* q = (const float*)d_in[0];
    const float* k = (const float*)d_in[1];
    const float* v = (const float*)d_in[2];
    float* o = (float*)d_out;

    prep_kernel<<<(B_ * N_ * D_ / 2) / NTP, NTP>>>(q, k, v);

    cudaFuncSetAttribute(attn_refine_kernel, cudaFuncAttributeMaxDynamicSharedMemorySize, SMEM_TOTAL);
    attn_refine_kernel<<<dim3(N_ / BM, B_), NT, SMEM_TOTAL>>>(q, k, v, o);
}

// round 13
// speedup vs baseline: 1.2701x; 1.2701x over previous
#include <cuda_runtime.h>
#include <cuda_fp16.h>
#include <cstdint>

#define B_  16
#define N_  2048
#define D_  128
#define BM  128
#define BN  64
#define NT  256
#define NTP 256
#define NTILES (N_/BN)        // 32
#define RS  272               // smem row stride (bytes)
#define TS  (64*RS)           // one 64x128 fp16 tile = 17408 B
#define CAP_W 192             // per-warp candidate cap
#define CAP_S 24              // per-row survivor cap
#define THR  8.5f             // log2-domain refinement window

// smem layout
#define SM_STAGES (4*TS)                   // {Kh,Vh} x 2 stages = 69632
#define SM_WCNT   SM_STAGES                // 8 ints (pad 128)
#define SM_SURCNT (SM_WCNT + 128)          // 128 ints
#define SM_MAX    (SM_SURCNT + 512)        // 128 floats
#define SM_SUR    (SM_MAX + 512)           // 128*CAP_S*8 = 24576
#define SM_CAND   (SM_SUR + 128*CAP_S*8)   // 8*CAP_W*8 = 12288
#define SMEM_TOTAL (SM_CAND + 8*CAP_W*8)   // 107648

// -------- static device scratch --------
__device__ __align__(256) __half g_Qh[B_*N_*D_];   // q * log2e, fp16
__device__ __align__(256) __half g_Kh[B_*N_*D_];
__device__ __align__(256) __half g_Vh[B_*N_*D_];

// -------- PTX helpers (compute_103-safe) --------
__device__ __forceinline__ uint32_t smem_u32(const void* p) {
    uint32_t a;
    asm("{ .reg .u64 t; cvta.to.shared.u64 t, %1; cvt.u32.u64 %0, t; }" : "=r"(a) : "l"(p));
    return a;
}
__device__ __forceinline__ void cpa16(uint32_t dst, const void* src) {
    asm volatile("cp.async.cg.shared.global [%0], [%1], 16;" :: "r"(dst), "l"(src) : "memory");
}
#define CP_COMMIT() asm volatile("cp.async.commit_group;" ::: "memory")
#define CP_WAIT(n)  asm volatile("cp.async.wait_group %0;" :: "n"(n) : "memory")

__device__ __forceinline__ void ldsm4(uint32_t* r, uint32_t a) {
    asm volatile("ldmatrix.sync.aligned.m8n8.x4.shared.b16 {%0,%1,%2,%3}, [%4];"
        : "=r"(r[0]), "=r"(r[1]), "=r"(r[2]), "=r"(r[3]) : "r"(a));
}
__device__ __forceinline__ void ldsm4t(uint32_t* r, uint32_t a) {
    asm volatile("ldmatrix.sync.aligned.m8n8.x4.trans.shared.b16 {%0,%1,%2,%3}, [%4];"
        : "=r"(r[0]), "=r"(r[1]), "=r"(r[2]), "=r"(r[3]) : "r"(a));
}
__device__ __forceinline__ void mma16816(float* c, const uint32_t* a, uint32_t b0, uint32_t b1) {
    asm volatile(
        "mma.sync.aligned.m16n8k16.row.col.f32.f16.f16.f32 "
        "{%0,%1,%2,%3}, {%4,%5,%6,%7}, {%8,%9}, {%0,%1,%2,%3};"
        : "+f"(c[0]), "+f"(c[1]), "+f"(c[2]), "+f"(c[3])
        : "r"(a[0]), "r"(a[1]), "r"(a[2]), "r"(a[3]), "r"(b0), "r"(b1));
}
__device__ __forceinline__ uint32_t pack_h2(float a, float b) {
    __half2 h = __floats2half2_rn(a, b);
    return *(uint32_t*)&h;
}
__device__ __forceinline__ float ex2(float x) {
    float r;
    asm("ex2.approx.ftz.f32 %0, %1;" : "=f"(r) : "f"(x));
    return r;
}

// -------- prep --------
__global__ void prep_kernel(const float* __restrict__ Q, const float* __restrict__ K,
                            const float* __restrict__ V) {
    size_t i = (size_t)blockIdx.x * blockDim.x + threadIdx.x;
    float2 q = ((const float2*)Q)[i];
    ((__half2*)g_Qh)[i] = __floats2half2_rn(q.x * 1.44269504089f, q.y * 1.44269504089f);
    float2 k = ((const float2*)K)[i];
    ((__half2*)g_Kh)[i] = __floats2half2_rn(k.x, k.y);
    float2 v = ((const float2*)V)[i];
    ((__half2*)g_Vh)[i] = __floats2half2_rn(v.x, v.y);
}

// -------- smem loaders --------
__device__ __forceinline__ void cp_tile64(uint32_t dstbase, const __half* src, int tid) {
#pragma unroll
    for (int i = 0; i < 4; i++) {
        int g = tid + i * NT;
        int row = g >> 4, c = g & 15;
        cpa16(dstbase + row * RS + c * 16, (const char*)src + row * 256 + c * 16);
    }
}
__device__ __forceinline__ void cp_tile128(uint32_t dstbase, const __half* src, int tid) {
#pragma unroll
    for (int i = 0; i < 8; i++) {
        int g = tid + i * NT;
        int row = g >> 4, c = g & 15;
        cpa16(dstbase + row * RS + c * 16, (const char*)src + row * 256 + c * 16);
    }
}
__device__ __forceinline__ void issue_group(uint32_t sb, size_t kvbase, int u, int tid) {
    size_t off = kvbase + (size_t)u * BN * D_;
    uint32_t st = sb + (uint32_t)(u & 1) * (2 * TS);
    cp_tile64(st,      g_Kh + off, tid);
    cp_tile64(st + TS, g_Vh + off, tid);
}

// -------- main attention kernel --------
__global__ void __launch_bounds__(NT, 1)
attn_refine_kernel(const float* __restrict__ Qf, const float* __restrict__ Kf,
                   const float* __restrict__ Vf, float* __restrict__ O)
{
    extern __shared__ __align__(1024) char smem[];
    uint32_t sb = smem_u32(smem);
    int*   wcnt   = (int*)(smem + SM_WCNT);
    int*   surcnt = (int*)(smem + SM_SURCNT);
    float* smax   = (float*)(smem + SM_MAX);
    float2* sur   = (float2*)(smem + SM_SUR);
    unsigned long long* cand = (unsigned long long*)(smem + SM_CAND);

    const int tid  = threadIdx.x;
    const int warp = tid >> 5;
    const int lane = tid & 31;
    const int qt = blockIdx.x;
    const int b  = blockIdx.y;

    const int m0 = warp * 16;
    const uint32_t qrow = m0 + (lane & 7) + ((lane & 8) ? 8 : 0);
    const uint32_t krow = (lane & 7) + ((lane & 16) ? 8 : 0);
    const uint32_t kcol = (lane & 8) ? 16 : 0;
    const uint32_t vrow = (lane & 7) + ((lane & 8) ? 8 : 0);
    const uint32_t vcol = (lane & 16) ? 16 : 0;
    const int lrow0 = m0 + (lane >> 2);
    const int lrow1 = lrow0 + 8;
    const int growbase = b * N_ + qt * BM;

    if (tid < 128) surcnt[tid] = 0;
    if (tid < 8)   wcnt[tid] = 0;

    // ---- stage Q, hoist fragments, recycle ----
    const size_t qoff = ((size_t)b * N_ + (size_t)qt * BM) * D_;
    cp_tile128(sb, g_Qh + qoff, tid);
    CP_COMMIT();
    CP_WAIT(0);
    __syncthreads();

    uint32_t qfh[8][4];
    {
        const uint32_t aq = sb + qrow * RS + ((lane & 16) ? 16 : 0);
#pragma unroll
        for (int k = 0; k < 8; k++) ldsm4(qfh[k], aq + k * 32);
    }
    __syncthreads();

    const size_t kvbase = (size_t)b * N_ * D_;
    issue_group(sb, kvbase, 0, tid); CP_COMMIT();
    issue_group(sb, kvbase, 1, tid); CP_COMMIT();

    float o[16][4];
#pragma unroll
    for (int i = 0; i < 16; i++)
#pragma unroll
        for (int j = 0; j < 4; j++) o[i][j] = 0.f;
    float m0r = -INFINITY, m1r = -INFINITY, l0 = 0.f, l1 = 0.f;

    CP_WAIT(1);
    __syncthreads();

    for (int t = 0; t < NTILES; t++) {
        const uint32_t st  = sb + (uint32_t)(t & 1) * (2 * TS);
        const uint32_t akh = st + krow * RS + kcol;
        const uint32_t avh = st + TS + vrow * RS + vcol;

        // ---- S(t) = Qh Kh^T (1 term, log2 units) ----
        float s[8][4];
#pragma unroll
        for (int i = 0; i < 8; i++)
#pragma unroll
            for (int j = 0; j < 4; j++) s[i][j] = 0.f;
#pragma unroll
        for (int k = 0; k < 8; k++) {
#pragma unroll
            for (int p = 0; p < 4; p++) {
                uint32_t bh[4];
                ldsm4(bh, akh + p * (16 * RS) + k * 32);
                mma16816(s[2*p],   qfh[k], bh[0], bh[1]);
                mma16816(s[2*p+1], qfh[k], bh[2], bh[3]);
            }
        }

        // ---- row max (thread-local kept for detection gate) ----
        float tmx0 = s[0][0], tmx1 = s[0][2];
#pragma unroll
        for (int nt = 0; nt < 8; nt++) {
            tmx0 = fmaxf(tmx0, fmaxf(s[nt][0], s[nt][1]));
            tmx1 = fmaxf(tmx1, fmaxf(s[nt][2], s[nt][3]));
        }
        float mx0 = fmaxf(tmx0, __shfl_xor_sync(0xffffffffu, tmx0, 1));
        mx0 = fmaxf(mx0, __shfl_xor_sync(0xffffffffu, mx0, 2));
        float mx1 = fmaxf(tmx1, __shfl_xor_sync(0xffffffffu, tmx1, 1));
        mx1 = fmaxf(mx1, __shfl_xor_sync(0xffffffffu, mx1, 2));
        float mn0 = fmaxf(m0r, mx0), mn1 = fmaxf(m1r, mx1);

        // ---- ballot-gated candidate detection ----
        {
            float thr0 = mn0 - THR, thr1 = mn1 - THR;
            bool anyT = (tmx0 > thr0) || (tmx1 > thr1);
            if (__ballot_sync(0xffffffffu, anyT) != 0u) {
#pragma unroll
                for (int nt = 0; nt < 8; nt++) {
#pragma unroll
                    for (int e = 0; e < 4; e++) {
                        float sv = s[nt][e];
                        bool pr = sv > ((e < 2) ? thr0 : thr1);
                        if (__ballot_sync(0xffffffffu, pr) != 0u) {
                            if (pr) {
                                int lr = (e < 2) ? lrow0 : lrow1;
                                int j = t * 64 + (nt >> 1) * 16 + (nt & 1) * 8
                                        + 2 * (lane & 3) + (e & 1);
                                int ix = atomicAdd(&wcnt[warp], 1);
                                if (ix < CAP_W)
                                    cand[warp * CAP_W + ix] =
                                        ((unsigned long long)__float_as_uint(sv) << 32)
                                        | (unsigned)((lr << 11) | j);
                            }
                        }
                    }
                }
            }
        }

        // ---- online softmax ----
        float c0 = ex2(m0r - mn0), c1 = ex2(m1r - mn1);
        m0r = mn0; m1r = mn1;
        float a0 = 0.f, a1 = 0.f;
#pragma unroll
        for (int nt = 0; nt < 8; nt++) {
            s[nt][0] = ex2(s[nt][0] - mn0); a0 += s[nt][0];
            s[nt][1] = ex2(s[nt][1] - mn0); a0 += s[nt][1];
            s[nt][2] = ex2(s[nt][2] - mn1); a1 += s[nt][2];
            s[nt][3] = ex2(s[nt][3] - mn1); a1 += s[nt][3];
        }
        l0 = l0 * c0 + a0;
        l1 = l1 * c1 + a1;
#pragma unroll
        for (int nt = 0; nt < 16; nt++) {
            o[nt][0] *= c0; o[nt][1] *= c0;
            o[nt][2] *= c1; o[nt][3] *= c1;
        }

        // ---- pack P and PV ----
        uint32_t pha[4][4];
#pragma unroll
        for (int js = 0; js < 4; js++) {
            const float* s0p = s[2*js];
            const float* s1p = s[2*js+1];
            pha[js][0] = pack_h2(s0p[0], s0p[1]);
            pha[js][1] = pack_h2(s0p[2], s0p[3]);
            pha[js][2] = pack_h2(s1p[0], s1p[1]);
            pha[js][3] = pack_h2(s1p[2], s1p[3]);
        }
#pragma unroll
        for (int js = 0; js < 4; js++) {
#pragma unroll
            for (int p = 0; p < 8; p++) {
                uint32_t vh[4];
                ldsm4t(vh, avh + js * (16 * RS) + p * 32);
                mma16816(o[2*p],   pha[js], vh[0], vh[1]);
                mma16816(o[2*p+1], pha[js], vh[2], vh[3]);
            }
        }

        // ---- rotate pipeline ----
        __syncthreads();
        if (t + 2 < NTILES) {
            issue_group(sb, kvbase, t + 2, tid);
            CP_COMMIT();
            CP_WAIT(1);
        } else {
            CP_COMMIT();
            CP_WAIT(0);
        }
        __syncthreads();
    }

    // ================= refinement =================
    // publish final row maxima
    if ((lane & 3) == 0) {
        smax[lrow0] = m0r;
        smax[lrow1] = m1r;
    }
    __syncthreads();

    // phase 1: lane-parallel exact rescoring of this warp's candidate list
    {
        const unsigned long long* wc = cand + warp * CAP_W;
        int nw = min(wcnt[warp], CAP_W);
        for (int c = lane; c < nw; c += 32) {
            unsigned long long pk = wc[c];
            float sap = __uint_as_float((uint32_t)(pk >> 32));
            int lrj = (int)(pk & 0xffffffffu);
            int lr = lrj >> 11, j = lrj & 2047;
            float mf = smax[lr];
            if (sap > mf - THR) {
                const float4* q4 = (const float4*)(Qf + (size_t)(growbase + lr) * D_);
                const float4* k4 = (const float4*)(Kf + ((size_t)b * N_ + j) * D_);
                float dot = 0.f;
#pragma unroll 8
                for (int d = 0; d < 32; d++) {
                    float4 qa = q4[d], kb = k4[d];
                    dot += qa.x * kb.x + qa.y * kb.y + qa.z * kb.z + qa.w * kb.w;
                }
                float sex = dot * 1.44269504089f;
                float dp = ex2(sex - mf) - ex2(sap - mf);
                int ix = atomicAdd(&surcnt[lr], 1);
                if (ix < CAP_S) sur[lr * CAP_S + ix] = make_float2(dp, __int_as_float(j));
            }
        }
    }
    __syncthreads();

    // phase 2: owner threads apply v-updates and l fix
    const int cbase2 = 2 * (lane & 3);
    float dl0 = 0.f, dl1 = 0.f;
#pragma unroll
    for (int h = 0; h < 2; h++) {
        int lr = (h ? lrow1 : lrow0);
        int n = min(surcnt[lr], CAP_S);
        for (int c = 0; c < n; c++) {
            float2 e = sur[lr * CAP_S + c];
            float dp = e.x;
            int j = __float_as_int(e.y);
            if (h) dl1 += dp; else dl0 += dp;
            const float* vrowp = Vf + ((size_t)b * N_ + j) * D_;
#pragma unroll
            for (int nt = 0; nt < 16; nt++) {
                float2 vv = *(const float2*)(vrowp + nt * 8 + cbase2);
                o[nt][2*h]     += dp * vv.x;
                o[nt][2*h + 1] += dp * vv.y;
            }
        }
    }

    // ---- epilogue ----
    l0 += __shfl_xor_sync(0xffffffffu, l0, 1);
    l0 += __shfl_xor_sync(0xffffffffu, l0, 2);
    l1 += __shfl_xor_sync(0xffffffffu, l1, 1);
    l1 += __shfl_xor_sync(0xffffffffu, l1, 2);
    l0 += dl0;
    l1 += dl1;
    float inv0 = 1.0f / l0, inv1 = 1.0f / l1;

    size_t row0 = (size_t)b * N_ + (size_t)qt * BM + m0 + (lane >> 2);
    float* p0 = O + row0 * D_;
    float* p1 = p0 + 8 * D_;
#pragma unroll
    for (int nt = 0; nt < 16; nt++) {
        int c = nt * 8 + cbase2;
        *(float2*)(p0 + c) = make_float2(o[nt][0] * inv0, o[nt][1] * inv0);
        *(float2*)(p1 + c) = make_float2(o[nt][2] * inv1, o[nt][3] * inv1);
    }
}

// -------- launcher --------
extern "C" void kernel_launch(void* const* d_in, const int* in_sizes, int n_in,
                              void* d_out, int out_size) {
    const float* q = (const float*)d_in[0];
    const float* k = (const float*)d_in[1];
    const float* v = (const float*)d_in[2];
    float* o = (float*)d_out;

    prep_kernel<<<(B_ * N_ * D_ / 2) / NTP, NTP>>>(q, k, v);

    cudaFuncSetAttribute(attn_refine_kernel, cudaFuncAttributeMaxDynamicSharedMemorySize, SMEM_TOTAL);
    attn_refine_kernel<<<dim3(N_ / BM, B_), NT, SMEM_TOTAL>>>(q, k, v, o);
}